// round 16
// baseline (speedup 1.0000x reference)
#include <cuda_runtime.h>

#define BSZ 2
#define TSEQ 2048
#define CDIM 1024
#define HN 16
#define DH 64

// Scratch (allocation-free rule: __device__ globals). All tf32 bit-patterns.
__device__ unsigned g_x32[(size_t)BSZ * TSEQ * CDIM];        // x as tf32 [M][K]
__device__ unsigned g_wa32[(size_t)CDIM * 3 * CDIM];         // w_attn^T tf32 [3C][C]
__device__ unsigned g_wp32[(size_t)CDIM * CDIM];             // w_proj^T tf32 [C][C]
__device__ unsigned g_qkv[(size_t)BSZ * TSEQ * 3 * CDIM];    // qkv as tf32
__device__ unsigned g_y[(size_t)BSZ * TSEQ * CDIM];          // y as tf32

__device__ __forceinline__ unsigned f2tf32(float f) {
    unsigned r;
    asm("cvt.rna.tf32.f32 %0, %1;" : "=r"(r) : "f"(f));
    return r;
}

__device__ __forceinline__ void mma_tf32(float* c, const unsigned* a, const unsigned* b) {
    asm volatile(
        "mma.sync.aligned.m16n8k8.row.col.f32.tf32.tf32.f32 "
        "{%0,%1,%2,%3}, {%4,%5,%6,%7}, {%8,%9}, {%0,%1,%2,%3};"
        : "+f"(c[0]), "+f"(c[1]), "+f"(c[2]), "+f"(c[3])
        : "r"(a[0]), "r"(a[1]), "r"(a[2]), "r"(a[3]), "r"(b[0]), "r"(b[1]));
}

__device__ __forceinline__ void cp_async16(void* smem, const void* gmem) {
    unsigned saddr = (unsigned)__cvta_generic_to_shared(smem);
    asm volatile("cp.async.cg.shared.global [%0], [%1], 16;" :: "r"(saddr), "l"(gmem));
}
__device__ __forceinline__ void cp_commit() { asm volatile("cp.async.commit_group;"); }
__device__ __forceinline__ void cp_wait1()  { asm volatile("cp.async.wait_group 1;"); }
__device__ __forceinline__ void cp_wait0()  { asm volatile("cp.async.wait_group 0;"); }

__device__ __forceinline__ void ldm_x4(unsigned* r, const void* smem) {
    unsigned saddr = (unsigned)__cvta_generic_to_shared(smem);
    asm volatile("ldmatrix.sync.aligned.m8n8.x4.shared.b16 {%0,%1,%2,%3}, [%4];"
        : "=r"(r[0]), "=r"(r[1]), "=r"(r[2]), "=r"(r[3]) : "r"(saddr));
}
__device__ __forceinline__ void ldm_x2(unsigned* r, const void* smem) {
    unsigned saddr = (unsigned)__cvta_generic_to_shared(smem);
    asm volatile("ldmatrix.sync.aligned.m8n8.x2.shared.b16 {%0,%1}, [%2];"
        : "=r"(r[0]), "=r"(r[1]) : "r"(saddr));
}

// ---------------------------------------------------------------------------
// fp32 -> tf32 pre-convert (vectorized)
// ---------------------------------------------------------------------------
__global__ __launch_bounds__(256) void cvt_tf32(
    const float* __restrict__ in, unsigned* __restrict__ out, int n4)
{
    int i = blockIdx.x * 256 + threadIdx.x;
    if (i < n4) {
        float4 v = *(const float4*)(in + (size_t)i * 4);
        uint4 u;
        u.x = f2tf32(v.x); u.y = f2tf32(v.y);
        u.z = f2tf32(v.z); u.w = f2tf32(v.w);
        *(uint4*)(out + (size_t)i * 4) = u;
    }
}

// ---------------------------------------------------------------------------
// fp32 [K][N] -> tf32 [N][K] transpose-convert (32x32 tiles, block 32x8)
// ---------------------------------------------------------------------------
__global__ __launch_bounds__(256) void tpose_tf32(
    const float* __restrict__ in, unsigned* __restrict__ out, int K, int N)
{
    __shared__ unsigned tile[32][33];
    const int tx = threadIdx.x, ty = threadIdx.y;
    const int bx = blockIdx.x * 32;   // N offset
    const int by = blockIdx.y * 32;   // K offset
#pragma unroll
    for (int j = 0; j < 32; j += 8)
        tile[ty + j][tx] = f2tf32(in[(size_t)(by + ty + j) * N + bx + tx]);
    __syncthreads();
#pragma unroll
    for (int j = 0; j < 32; j += 8)
        out[(size_t)(bx + ty + j) * K + by + tx] = tile[tx][ty + j];
}

// ---------------------------------------------------------------------------
// tf32 tensor-core GEMM: 64x64 warp tiles (4 warps, CTA 128x128),
// 2-stage cp.async, BOTH operands K-major with ldmatrix.x4 fragments.
// C[M,N] = A[M,K] @ Bt[N,K]^T + bias[N].
// ---------------------------------------------------------------------------
#define LDA 36
#define STG_T (128 * LDA)
#define GEMM_SMEM (4 * STG_T)   // 2 stages x (A + B)

template <bool OUT_TF32>
__global__ __launch_bounds__(128, 2) void gemm_tf32_bias(
    const unsigned* __restrict__ A, const unsigned* __restrict__ Bt,
    const float* __restrict__ bias, void* __restrict__ Cv,
    int M, int N, int K)
{
    extern __shared__ unsigned sg[];
    unsigned* sA = sg;                    // [2][128][LDA]
    unsigned* sB = sg + 2 * STG_T;        // [2][128][LDA]

    const int tid    = threadIdx.x;
    const int wid    = tid >> 5;          // 0..3
    const int lane   = tid & 31;
    const int g      = lane >> 2;
    const int t      = lane & 3;
    const int warp_m = wid >> 1;          // 0..1
    const int warp_n = wid & 1;           // 0..1
    const int bm     = blockIdx.y;
    const int bn     = blockIdx.x;

    float acc[4][8][4];
#pragma unroll
    for (int i = 0; i < 4; i++)
#pragma unroll
        for (int j = 0; j < 8; j++)
#pragma unroll
            for (int v = 0; v < 4; v++) acc[i][j][v] = 0.f;

    const int wm = warp_m * 64;
    const int wn = warp_n * 64;
    const int NK = K >> 5;

    const int rowL   = lane & 15;                       // A-frag ldm rows
    const int colOff = (lane >> 4) << 2;                // A-frag col half
    const int rowB   = ((lane >> 4) & 1) * 8 + (lane & 7);  // B-frag ldm rows
    const int colB   = (lane & 8) ? 4 : 0;              // B-frag col half

    auto load_tiles = [&](int buf, int k0) {
        unsigned* dA = sA + buf * STG_T;
        unsigned* dB = sB + buf * STG_T;
#pragma unroll
        for (int it = 0; it < 8; it++) {
            int gidx = it * 128 + tid;
            int r = gidx >> 3, c = (gidx & 7) << 2;
            cp_async16(&dA[r * LDA + c], A  + (size_t)(bm * 128 + r) * K + k0 + c);
        }
#pragma unroll
        for (int it = 0; it < 8; it++) {
            int gidx = it * 128 + tid;
            int r = gidx >> 3, c = (gidx & 7) << 2;
            cp_async16(&dB[r * LDA + c], Bt + (size_t)(bn * 128 + r) * K + k0 + c);
        }
        cp_commit();
    };

    load_tiles(0, 0);

    for (int i = 0; i < NK; i++) {
        if (i + 1 < NK) {
            load_tiles((i + 1) & 1, (i + 1) << 5);
            cp_wait1();
        } else {
            cp_wait0();
        }
        __syncthreads();

        const unsigned* cA = sA + (i & 1) * STG_T;
        const unsigned* cB = sB + (i & 1) * STG_T;

#pragma unroll
        for (int kk = 0; kk < 32; kk += 8) {
            unsigned af[4][4], bq[4][4];
#pragma unroll
            for (int mt = 0; mt < 4; mt++)
                ldm_x4(af[mt], &cA[(wm + mt * 16 + rowL) * LDA + kk + colOff]);
#pragma unroll
            for (int np = 0; np < 4; np++)
                ldm_x4(bq[np], &cB[(wn + np * 16 + rowB) * LDA + kk + colB]);
#pragma unroll
            for (int mt = 0; mt < 4; mt++)
#pragma unroll
                for (int nt = 0; nt < 8; nt++)
                    mma_tf32(acc[mt][nt], af[mt], bq[nt >> 1] + (nt & 1) * 2);
        }
        __syncthreads();
    }

    // ---- epilogue: bias + store ----
#pragma unroll
    for (int nt = 0; nt < 8; nt++) {
        int col = bn * 128 + wn + nt * 8 + t * 2;
        float b0 = bias[col], b1 = bias[col + 1];
#pragma unroll
        for (int mt = 0; mt < 4; mt++) {
            int row0 = bm * 128 + wm + mt * 16 + g;
            float v00 = acc[mt][nt][0] + b0, v01 = acc[mt][nt][1] + b1;
            float v10 = acc[mt][nt][2] + b0, v11 = acc[mt][nt][3] + b1;
            if (OUT_TF32) {
                unsigned* C = (unsigned*)Cv;
                uint2 u0, u1;
                u0.x = f2tf32(v00); u0.y = f2tf32(v01);
                u1.x = f2tf32(v10); u1.y = f2tf32(v11);
                *(uint2*)(C + (size_t)row0 * N + col)       = u0;
                *(uint2*)(C + (size_t)(row0 + 8) * N + col) = u1;
            } else {
                float* C = (float*)Cv;
                float2 o0, o1;
                o0.x = v00; o0.y = v01;
                o1.x = v10; o1.y = v11;
                *(float2*)(C + (size_t)row0 * N + col)       = o0;
                *(float2*)(C + (size_t)(row0 + 8) * N + col) = o1;
            }
        }
    }
}

// ---------------------------------------------------------------------------
// Flash attention v5 (R15 winner, unchanged): CTA = 128 q-rows,
// 4 warps x m32 (2 x m16 sub-tiles), 64-key tiles double-buffered.
// smem 106.5 KB -> 2 CTAs/SM. Heavy-first.
// ---------------------------------------------------------------------------
#define LDQ 68
#define LDK 68
#define LDV 72
#define ATTN_SMEM (128 * LDQ + 2 * 64 * LDK + 2 * 64 * LDV)   // 26624 u32

__global__ __launch_bounds__(128, 2) void attn_flash_mma(
    const unsigned* __restrict__ qkv, unsigned* __restrict__ y)
{
    extern __shared__ unsigned smu[];
    unsigned* sQ = smu;                      // [128][LDQ]; reused as P staging
    unsigned* sK = smu + 128 * LDQ;          // [2][64][LDK]
    unsigned* sV = sK + 2 * 64 * LDK;        // [2][64][LDV]

    const int qb   = (int)gridDim.x - 1 - (int)blockIdx.x;   // heavy-first
    const int h    = blockIdx.y;
    const int b    = blockIdx.z;
    const int tid  = threadIdx.x;
    const int wid  = tid >> 5;               // 0..3
    const int lane = tid & 31;
    const int g    = lane >> 2;
    const int t    = lane & 3;
    const int wq   = wid * 32;               // warp's 32-row slice

    const size_t rs = 3 * CDIM;
    const size_t baseQ = ((size_t)(b * TSEQ + qb * 128)) * rs + h * DH;

    // ---- load Q tile [128][64] (already tf32), 128 threads ----
#pragma unroll
    for (int it = 0; it < 16; it++) {
        int idx = it * 128 + tid;
        int r = idx >> 4, c = (idx & 15) << 2;
        *(uint4*)&sQ[r * LDQ + c] = *(const uint4*)(qkv + baseQ + (size_t)r * rs + c);
    }

    const int nkb = 2 * qb + 2;              // 64-key tiles

    auto load_kv = [&](int buf, int kb) {
        const size_t baseK = ((size_t)(b * TSEQ + kb * 64)) * rs + CDIM + h * DH;
        unsigned* dK = sK + buf * 64 * LDK;
        unsigned* dV = sV + buf * 64 * LDV;
#pragma unroll
        for (int it = 0; it < 8; it++) {
            int idx = it * 128 + tid;
            int r = idx >> 4, c = (idx & 15) << 2;
            cp_async16(&dK[r * LDK + c], qkv + baseK + (size_t)r * rs + c);
            cp_async16(&dV[r * LDV + c], qkv + baseK + CDIM + (size_t)r * rs + c);
        }
        cp_commit();
    };

    load_kv(0, 0);
    __syncthreads();

    // ---- Q fragments into registers: 2 m16 sub-tiles ----
    const int rowL   = lane & 15;
    const int colOff = (lane >> 4) << 2;
    unsigned qf[8][2][4];
#pragma unroll
    for (int kk = 0; kk < 8; kk++)
#pragma unroll
        for (int mt = 0; mt < 2; mt++)
            ldm_x4(qf[kk][mt], &sQ[(wq + mt * 16 + rowL) * LDQ + kk * 8 + colOff]);

    unsigned* sP = sQ + wq * LDQ;   // per-warp P staging [32][LDQ]

    float o[2][8][4];
#pragma unroll
    for (int mt = 0; mt < 2; mt++)
#pragma unroll
        for (int nt = 0; nt < 8; nt++)
#pragma unroll
            for (int j = 0; j < 4; j++) o[mt][nt][j] = 0.f;
    float mS[2][2], lS[2][2];
#pragma unroll
    for (int mt = 0; mt < 2; mt++) {
        mS[mt][0] = -1e30f; mS[mt][1] = -1e30f;
        lS[mt][0] = 0.f;    lS[mt][1] = 0.f;
    }

    const int rowW = qb * 128 + wq;          // warp's min global q row
    const int rowK   = lane & 7;
    const int colKof = (lane & 8) ? 4 : 0;

    for (int kb = 0; kb < nkb; kb++) {
        if (kb + 1 < nkb) {
            load_kv((kb + 1) & 1, kb + 1);
            cp_wait1();
        } else {
            cp_wait0();
        }
        __syncthreads();

        const bool active = (rowW + 31 >= kb * 64);
        if (active) {
            const unsigned* cK = sK + (kb & 1) * 64 * LDK;
            const unsigned* cV = sV + (kb & 1) * 64 * LDV;

            // ---- S = Q @ K^T : K frag shared across 2 m-tiles ----
            float s[2][8][4];
#pragma unroll
            for (int mt = 0; mt < 2; mt++)
#pragma unroll
                for (int nt = 0; nt < 8; nt++)
#pragma unroll
                    for (int j = 0; j < 4; j++) s[mt][nt][j] = 0.f;

#pragma unroll
            for (int kk = 0; kk < 8; kk++) {
#pragma unroll
                for (int nt = 0; nt < 8; nt++) {
                    unsigned bf[2];
                    ldm_x2(bf, &cK[(nt * 8 + rowK) * LDK + kk * 8 + colKof]);
                    mma_tf32(s[0][nt], qf[kk][0], bf);
                    mma_tf32(s[1][nt], qf[kk][1], bf);
                }
            }

            // ---- scale + causal mask ----
            const float scale = 0.125f;
            if (kb * 64 + 63 > rowW) {
#pragma unroll
                for (int mt = 0; mt < 2; mt++) {
                    int r0 = rowW + mt * 16 + g;
                    int r1 = r0 + 8;
#pragma unroll
                    for (int nt = 0; nt < 8; nt++) {
                        int c0 = kb * 64 + nt * 8 + 2 * t;
                        s[mt][nt][0] = (c0     <= r0) ? s[mt][nt][0] * scale : -1e30f;
                        s[mt][nt][1] = (c0 + 1 <= r0) ? s[mt][nt][1] * scale : -1e30f;
                        s[mt][nt][2] = (c0     <= r1) ? s[mt][nt][2] * scale : -1e30f;
                        s[mt][nt][3] = (c0 + 1 <= r1) ? s[mt][nt][3] * scale : -1e30f;
                    }
                }
            } else {
#pragma unroll
                for (int mt = 0; mt < 2; mt++)
#pragma unroll
                    for (int nt = 0; nt < 8; nt++)
#pragma unroll
                        for (int j = 0; j < 4; j++) s[mt][nt][j] *= scale;
            }

            // ---- online softmax (4 row-slots per thread) ----
#pragma unroll
            for (int mt = 0; mt < 2; mt++) {
                float mx0 = -1e30f, mx1 = -1e30f;
#pragma unroll
                for (int nt = 0; nt < 8; nt++) {
                    mx0 = fmaxf(mx0, fmaxf(s[mt][nt][0], s[mt][nt][1]));
                    mx1 = fmaxf(mx1, fmaxf(s[mt][nt][2], s[mt][nt][3]));
                }
                mx0 = fmaxf(mx0, __shfl_xor_sync(0xffffffffu, mx0, 1));
                mx0 = fmaxf(mx0, __shfl_xor_sync(0xffffffffu, mx0, 2));
                mx1 = fmaxf(mx1, __shfl_xor_sync(0xffffffffu, mx1, 1));
                mx1 = fmaxf(mx1, __shfl_xor_sync(0xffffffffu, mx1, 2));

                float mn0 = fmaxf(mS[mt][0], mx0), mn1 = fmaxf(mS[mt][1], mx1);
                float a0 = __expf(mS[mt][0] - mn0), a1 = __expf(mS[mt][1] - mn1);
                mS[mt][0] = mn0; mS[mt][1] = mn1;

                float sum0 = 0.f, sum1 = 0.f;
#pragma unroll
                for (int nt = 0; nt < 8; nt++) {
                    s[mt][nt][0] = __expf(s[mt][nt][0] - mn0);
                    s[mt][nt][1] = __expf(s[mt][nt][1] - mn0);
                    s[mt][nt][2] = __expf(s[mt][nt][2] - mn1);
                    s[mt][nt][3] = __expf(s[mt][nt][3] - mn1);
                    sum0 += s[mt][nt][0] + s[mt][nt][1];
                    sum1 += s[mt][nt][2] + s[mt][nt][3];
                }
                sum0 += __shfl_xor_sync(0xffffffffu, sum0, 1);
                sum0 += __shfl_xor_sync(0xffffffffu, sum0, 2);
                sum1 += __shfl_xor_sync(0xffffffffu, sum1, 1);
                sum1 += __shfl_xor_sync(0xffffffffu, sum1, 2);
                lS[mt][0] = lS[mt][0] * a0 + sum0;
                lS[mt][1] = lS[mt][1] * a1 + sum1;

#pragma unroll
                for (int nt = 0; nt < 8; nt++) {
                    o[mt][nt][0] *= a0; o[mt][nt][1] *= a0;
                    o[mt][nt][2] *= a1; o[mt][nt][3] *= a1;
                }
            }

            // ---- stage P (tf32) into per-warp smem [32][LDQ] ----
            __syncwarp();
#pragma unroll
            for (int mt = 0; mt < 2; mt++)
#pragma unroll
                for (int nt = 0; nt < 8; nt++) {
                    int c0 = nt * 8 + 2 * t;
                    uint2 u0, u1;
                    u0.x = f2tf32(s[mt][nt][0]); u0.y = f2tf32(s[mt][nt][1]);
                    u1.x = f2tf32(s[mt][nt][2]); u1.y = f2tf32(s[mt][nt][3]);
                    *(uint2*)&sP[(mt * 16 + g) * LDQ + c0]     = u0;
                    *(uint2*)&sP[(mt * 16 + 8 + g) * LDQ + c0] = u1;
                }
            __syncwarp();

            // ---- O += P @ V : V frag shared across 2 m-tiles ----
#pragma unroll
            for (int kk = 0; kk < 8; kk++) {
                unsigned pf[2][4];
                ldm_x4(pf[0], &sP[rowL * LDQ + kk * 8 + colOff]);
                ldm_x4(pf[1], &sP[(16 + rowL) * LDQ + kk * 8 + colOff]);
#pragma unroll
                for (int nt = 0; nt < 8; nt++) {
                    unsigned bf[2];
                    bf[0] = cV[(kk * 8 + t) * LDV + nt * 8 + g];
                    bf[1] = cV[(kk * 8 + t + 4) * LDV + nt * 8 + g];
                    mma_tf32(o[0][nt], pf[0], bf);
                    mma_tf32(o[1][nt], pf[1], bf);
                }
            }
        }
        __syncthreads();
    }

    // ---- epilogue: normalize, write y (tf32 bits) ----
#pragma unroll
    for (int mt = 0; mt < 2; mt++) {
        float inv0 = 1.0f / lS[mt][0], inv1 = 1.0f / lS[mt][1];
        int r0 = rowW + mt * 16 + g;
        const size_t yr0 = ((size_t)(b * TSEQ) + r0) * CDIM + h * DH;
        const size_t yr1 = ((size_t)(b * TSEQ) + r0 + 8) * CDIM + h * DH;
#pragma unroll
        for (int nt = 0; nt < 8; nt++) {
            int c0 = nt * 8 + 2 * t;
            uint2 v0, v1;
            v0.x = f2tf32(o[mt][nt][0] * inv0); v0.y = f2tf32(o[mt][nt][1] * inv0);
            v1.x = f2tf32(o[mt][nt][2] * inv1); v1.y = f2tf32(o[mt][nt][3] * inv1);
            *(uint2*)(y + yr0 + c0) = v0;
            *(uint2*)(y + yr1 + c0) = v1;
        }
    }
}

// ---------------------------------------------------------------------------
extern "C" void kernel_launch(void* const* d_in, const int* in_sizes, int n_in,
                              void* d_out, int out_size)
{
    const float* x      = (const float*)d_in[0];
    const float* w_attn = (const float*)d_in[1];
    const float* b_attn = (const float*)d_in[2];
    const float* w_proj = (const float*)d_in[3];
    const float* b_proj = (const float*)d_in[4];
    float* out = (float*)d_out;

    unsigned *x32, *waT, *wpT, *qkv, *yb;
    cudaGetSymbolAddress((void**)&x32, g_x32);
    cudaGetSymbolAddress((void**)&waT, g_wa32);
    cudaGetSymbolAddress((void**)&wpT, g_wp32);
    cudaGetSymbolAddress((void**)&qkv, g_qkv);
    cudaGetSymbolAddress((void**)&yb, g_y);

    const int smem_gemm = GEMM_SMEM * (int)sizeof(unsigned);   // 73728 B
    const int smem_attn = ATTN_SMEM * (int)sizeof(unsigned);   // 106496 B
    cudaFuncSetAttribute(gemm_tf32_bias<true>,
                         cudaFuncAttributeMaxDynamicSharedMemorySize, smem_gemm);
    cudaFuncSetAttribute(gemm_tf32_bias<false>,
                         cudaFuncAttributeMaxDynamicSharedMemorySize, smem_gemm);
    cudaFuncSetAttribute(attn_flash_mma,
                         cudaFuncAttributeMaxDynamicSharedMemorySize, smem_attn);

    const int M = BSZ * TSEQ;   // 4096

    // 0) x -> tf32; weights -> transposed tf32 [N][K]
    const int nx = M * CDIM / 4;
    cvt_tf32<<<(nx + 255) / 256, 256>>>(x, x32, nx);
    tpose_tf32<<<dim3(3 * CDIM / 32, CDIM / 32), dim3(32, 8)>>>(w_attn, waT, CDIM, 3 * CDIM);
    tpose_tf32<<<dim3(CDIM / 32, CDIM / 32), dim3(32, 8)>>>(w_proj, wpT, CDIM, CDIM);

    // 1) qkv = x @ w_attn + b_attn     [4096, 3072]  (tf32 out)
    gemm_tf32_bias<true><<<dim3((3 * CDIM) / 128, M / 128), 128, smem_gemm>>>(
        x32, waT, b_attn, qkv, M, 3 * CDIM, CDIM);

    // 2) flash attention -> y (tf32)   [4096, 1024]
    attn_flash_mma<<<dim3(TSEQ / 128, HN, BSZ), 128, smem_attn>>>(qkv, yb);

    // 3) out = y @ w_proj + b_proj     [4096, 1024]  (fp32 out)
    gemm_tf32_bias<false><<<dim3(CDIM / 128, M / 128), 128, smem_gemm>>>(
        yb, wpT, b_proj, out, M, CDIM, CDIM);
}

// round 17
// speedup vs baseline: 1.8194x; 1.8194x over previous
#include <cuda_runtime.h>
#include <cuda_fp16.h>

#define BSZ 2
#define TSEQ 2048
#define CDIM 1024
#define HN 16
#define DH 64

// Scratch (allocation-free rule: __device__ globals). fp16 data.
__device__ __half g_xh[(size_t)BSZ * TSEQ * CDIM];         // x fp16 [M][K]
__device__ __half g_wah[(size_t)CDIM * 3 * CDIM];          // w_attn fp16 [K][N]
__device__ __half g_wph[(size_t)CDIM * CDIM];              // w_proj fp16 [K][N]
__device__ __half g_qkv[(size_t)BSZ * TSEQ * 3 * CDIM];    // qkv fp16
__device__ __half g_y[(size_t)BSZ * TSEQ * CDIM];          // y fp16

__device__ __forceinline__ void mma_f16(float* c, const unsigned* a, const unsigned* b) {
    asm volatile(
        "mma.sync.aligned.m16n8k16.row.col.f32.f16.f16.f32 "
        "{%0,%1,%2,%3}, {%4,%5,%6,%7}, {%8,%9}, {%0,%1,%2,%3};"
        : "+f"(c[0]), "+f"(c[1]), "+f"(c[2]), "+f"(c[3])
        : "r"(a[0]), "r"(a[1]), "r"(a[2]), "r"(a[3]), "r"(b[0]), "r"(b[1]));
}

__device__ __forceinline__ void cp_async16(void* smem, const void* gmem) {
    unsigned saddr = (unsigned)__cvta_generic_to_shared(smem);
    asm volatile("cp.async.cg.shared.global [%0], [%1], 16;" :: "r"(saddr), "l"(gmem));
}
__device__ __forceinline__ void cp_commit() { asm volatile("cp.async.commit_group;"); }
__device__ __forceinline__ void cp_wait1()  { asm volatile("cp.async.wait_group 1;"); }
__device__ __forceinline__ void cp_wait0()  { asm volatile("cp.async.wait_group 0;"); }

__device__ __forceinline__ void ldm_x4(unsigned* r, const void* smem) {
    unsigned saddr = (unsigned)__cvta_generic_to_shared(smem);
    asm volatile("ldmatrix.sync.aligned.m8n8.x4.shared.b16 {%0,%1,%2,%3}, [%4];"
        : "=r"(r[0]), "=r"(r[1]), "=r"(r[2]), "=r"(r[3]) : "r"(saddr));
}
__device__ __forceinline__ void ldm_x4t(unsigned* r, const void* smem) {
    unsigned saddr = (unsigned)__cvta_generic_to_shared(smem);
    asm volatile("ldmatrix.sync.aligned.m8n8.x4.trans.shared.b16 {%0,%1,%2,%3}, [%4];"
        : "=r"(r[0]), "=r"(r[1]), "=r"(r[2]), "=r"(r[3]) : "r"(saddr));
}

__device__ __forceinline__ unsigned packh2(float lo, float hi) {
    __half2 h = __floats2half2_rn(lo, hi);
    return *(unsigned*)&h;
}

// ---------------------------------------------------------------------------
// fp32 -> fp16 pre-convert (8 elems/thread)
// ---------------------------------------------------------------------------
__global__ __launch_bounds__(256) void cvt_f16(
    const float* __restrict__ in, __half* __restrict__ out, int n8)
{
    int i = blockIdx.x * 256 + threadIdx.x;
    if (i < n8) {
        float4 v0 = *(const float4*)(in + (size_t)i * 8);
        float4 v1 = *(const float4*)(in + (size_t)i * 8 + 4);
        uint4 u;
        u.x = packh2(v0.x, v0.y);
        u.y = packh2(v0.z, v0.w);
        u.z = packh2(v1.x, v1.y);
        u.w = packh2(v1.z, v1.w);
        *(uint4*)(out + (size_t)i * 8) = u;
    }
}

// ---------------------------------------------------------------------------
// fp16 tensor-core GEMM: 64x64 warp tiles (4 warps, CTA 128x128), BK=32,
// 2-stage cp.async. A via ldm_x4, B ([K][N] layout) via ldm_x4.trans.
// C[M,N] = A[M,K] @ B[K,N] + bias[N].
// ---------------------------------------------------------------------------
#define LDAH 40
#define LDBH 136
#define STG_AH (128 * LDAH)
#define STG_BH (32 * LDBH)
#define GEMM_SMEM_B (2 * (STG_AH + STG_BH) * 2)   // 37888 bytes

template <bool OUT_F16>
__global__ __launch_bounds__(128, 2) void gemm_f16_bias(
    const __half* __restrict__ A, const __half* __restrict__ B,
    const float* __restrict__ bias, void* __restrict__ Cv,
    int M, int N, int K)
{
    extern __shared__ __half sh[];
    __half* sA = sh;                    // [2][128][LDAH]
    __half* sB = sh + 2 * STG_AH;       // [2][32][LDBH]

    const int tid    = threadIdx.x;
    const int wid    = tid >> 5;
    const int lane   = tid & 31;
    const int g      = lane >> 2;
    const int t      = lane & 3;
    const int warp_m = wid >> 1;
    const int warp_n = wid & 1;
    const int bm     = blockIdx.y;
    const int bn     = blockIdx.x;

    float acc[4][8][4];
#pragma unroll
    for (int i = 0; i < 4; i++)
#pragma unroll
        for (int j = 0; j < 8; j++)
#pragma unroll
            for (int v = 0; v < 4; v++) acc[i][j][v] = 0.f;

    const int wm = warp_m * 64;
    const int wn = warp_n * 64;
    const int NK = K >> 5;

    // A frag (non-trans): row lane&15, k-half by lane>>4
    const int aRow = lane & 15;
    const int aCol = ((lane >> 4) & 1) * 8;
    // B frag (trans): k-row = (lane&7) + ((lane>>3)&1)*8, n-half by lane>>4
    const int bRowK = (lane & 7) + ((lane >> 3) & 1) * 8;
    const int bColN = ((lane >> 4) & 1) * 8;

    auto load_tiles = [&](int buf, int k0) {
        __half* dA = sA + buf * STG_AH;
        __half* dB = sB + buf * STG_BH;
#pragma unroll
        for (int it = 0; it < 4; it++) {           // A: 128 x 32 fp16
            int gidx = it * 128 + tid;
            int r = gidx >> 2, c8 = (gidx & 3) * 8;
            cp_async16(&dA[r * LDAH + c8], A + (size_t)(bm * 128 + r) * K + k0 + c8);
        }
#pragma unroll
        for (int it = 0; it < 4; it++) {           // B: 32 x 128 fp16
            int gidx = it * 128 + tid;
            int r = gidx >> 4, c8 = (gidx & 15) * 8;
            cp_async16(&dB[r * LDBH + c8], B + (size_t)(k0 + r) * N + bn * 128 + c8);
        }
        cp_commit();
    };

    load_tiles(0, 0);

    for (int i = 0; i < NK; i++) {
        if (i + 1 < NK) {
            load_tiles((i + 1) & 1, (i + 1) << 5);
            cp_wait1();
        } else {
            cp_wait0();
        }
        __syncthreads();

        const __half* cA = sA + (i & 1) * STG_AH;
        const __half* cB = sB + (i & 1) * STG_BH;

#pragma unroll
        for (int kk = 0; kk < 2; kk++) {           // two k16 steps
            unsigned af[4][4], bq[4][4];
#pragma unroll
            for (int mt = 0; mt < 4; mt++)
                ldm_x4(af[mt], &cA[(wm + mt * 16 + aRow) * LDAH + kk * 16 + aCol]);
#pragma unroll
            for (int np = 0; np < 4; np++)
                ldm_x4t(bq[np], &cB[(kk * 16 + bRowK) * LDBH + wn + np * 16 + bColN]);
#pragma unroll
            for (int mt = 0; mt < 4; mt++)
#pragma unroll
                for (int nt = 0; nt < 8; nt++)
                    mma_f16(acc[mt][nt], af[mt], bq[nt >> 1] + (nt & 1) * 2);
        }
        __syncthreads();
    }

    // ---- epilogue: bias + store ----
#pragma unroll
    for (int nt = 0; nt < 8; nt++) {
        int col = bn * 128 + wn + nt * 8 + t * 2;
        float b0 = bias[col], b1 = bias[col + 1];
#pragma unroll
        for (int mt = 0; mt < 4; mt++) {
            int row0 = bm * 128 + wm + mt * 16 + g;
            float v00 = acc[mt][nt][0] + b0, v01 = acc[mt][nt][1] + b1;
            float v10 = acc[mt][nt][2] + b0, v11 = acc[mt][nt][3] + b1;
            if (OUT_F16) {
                __half* C = (__half*)Cv;
                *(unsigned*)(C + (size_t)row0 * N + col)       = packh2(v00, v01);
                *(unsigned*)(C + (size_t)(row0 + 8) * N + col) = packh2(v10, v11);
            } else {
                float* C = (float*)Cv;
                float2 o0, o1;
                o0.x = v00; o0.y = v01;
                o1.x = v10; o1.y = v11;
                *(float2*)(C + (size_t)row0 * N + col)       = o0;
                *(float2*)(C + (size_t)(row0 + 8) * N + col) = o1;
            }
        }
    }
}

// ---------------------------------------------------------------------------
// Flash attention fp16 (R15 structure): CTA = 128 q-rows, 4 warps x m32,
// 64-key tiles double-buffered, k16 MMAs. Q/K/P via ldm_x4, V via ldm_x4t.
// smem 55.3 KB -> 2 CTAs/SM. Heavy-first.
// ---------------------------------------------------------------------------
#define LDQH 72
#define LDKH 72
#define LDVH 72
#define ATTN_SMEM_H (128 * LDQH + 2 * 64 * LDKH + 2 * 64 * LDVH)   // fp16 units
#define ATTN_SMEM_B (ATTN_SMEM_H * 2)                              // 55296 bytes

__global__ __launch_bounds__(128, 2) void attn_flash_mma(
    const __half* __restrict__ qkv, __half* __restrict__ y)
{
    extern __shared__ __half smh[];
    __half* sQ = smh;                      // [128][LDQH]; reused as P staging
    __half* sK = smh + 128 * LDQH;         // [2][64][LDKH]
    __half* sV = sK + 2 * 64 * LDKH;       // [2][64][LDVH]

    const int qb   = (int)gridDim.x - 1 - (int)blockIdx.x;   // heavy-first
    const int h    = blockIdx.y;
    const int b    = blockIdx.z;
    const int tid  = threadIdx.x;
    const int lane = tid & 31;
    const int g    = lane >> 2;
    const int t    = lane & 3;
    const int wq   = (tid >> 5) * 32;      // warp's 32-row slice

    const size_t rs = 3 * CDIM;            // qkv row stride (fp16)
    const size_t baseQ = ((size_t)(b * TSEQ + qb * 128)) * rs + h * DH;

    // ---- load Q tile [128][64] fp16 ----
#pragma unroll
    for (int it = 0; it < 8; it++) {
        int idx = it * 128 + tid;
        int r = idx >> 3, c8 = (idx & 7) * 8;
        *(uint4*)&sQ[r * LDQH + c8] = *(const uint4*)(qkv + baseQ + (size_t)r * rs + c8);
    }

    const int nkb = 2 * qb + 2;            // 64-key tiles

    auto load_kv = [&](int buf, int kb) {
        const size_t baseK = ((size_t)(b * TSEQ + kb * 64)) * rs + CDIM + h * DH;
        __half* dK = sK + buf * 64 * LDKH;
        __half* dV = sV + buf * 64 * LDVH;
#pragma unroll
        for (int it = 0; it < 4; it++) {
            int idx = it * 128 + tid;
            int r = idx >> 3, c8 = (idx & 7) * 8;
            cp_async16(&dK[r * LDKH + c8], qkv + baseK + (size_t)r * rs + c8);
            cp_async16(&dV[r * LDVH + c8], qkv + baseK + CDIM + (size_t)r * rs + c8);
        }
        cp_commit();
    };

    load_kv(0, 0);
    __syncthreads();

    // fragment lane addressing
    const int aRow = lane & 15;
    const int aCol = ((lane >> 4) & 1) * 8;
    const int kRowN = ((lane >> 4) & 1) * 8 + (lane & 7);   // K non-trans pairs
    const int kColK = ((lane >> 3) & 1) * 8;
    const int vRowK = ((lane >> 3) & 1) * 8 + (lane & 7);   // V trans pairs
    const int vColN = ((lane >> 4) & 1) * 8;

    // ---- Q fragments: 4 k16-steps x 2 m16 sub-tiles ----
    unsigned qf[4][2][4];
#pragma unroll
    for (int kk = 0; kk < 4; kk++)
#pragma unroll
        for (int mt = 0; mt < 2; mt++)
            ldm_x4(qf[kk][mt], &sQ[(wq + mt * 16 + aRow) * LDQH + kk * 16 + aCol]);

    __half* sP = sQ + wq * LDQH;   // per-warp P staging [32][LDQH]

    float o[2][8][4];
#pragma unroll
    for (int mt = 0; mt < 2; mt++)
#pragma unroll
        for (int nt = 0; nt < 8; nt++)
#pragma unroll
            for (int j = 0; j < 4; j++) o[mt][nt][j] = 0.f;
    float mS[2][2], lS[2][2];
#pragma unroll
    for (int mt = 0; mt < 2; mt++) {
        mS[mt][0] = -1e30f; mS[mt][1] = -1e30f;
        lS[mt][0] = 0.f;    lS[mt][1] = 0.f;
    }

    const int rowW = qb * 128 + wq;

    for (int kb = 0; kb < nkb; kb++) {
        if (kb + 1 < nkb) {
            load_kv((kb + 1) & 1, kb + 1);
            cp_wait1();
        } else {
            cp_wait0();
        }
        __syncthreads();

        const bool active = (rowW + 31 >= kb * 64);
        if (active) {
            const __half* cK = sK + (kb & 1) * 64 * LDKH;
            const __half* cV = sV + (kb & 1) * 64 * LDVH;

            // ---- S = Q @ K^T (m32 x n64 x k64) ----
            float s[2][8][4];
#pragma unroll
            for (int mt = 0; mt < 2; mt++)
#pragma unroll
                for (int nt = 0; nt < 8; nt++)
#pragma unroll
                    for (int j = 0; j < 4; j++) s[mt][nt][j] = 0.f;

#pragma unroll
            for (int kk = 0; kk < 4; kk++) {
#pragma unroll
                for (int np = 0; np < 4; np++) {
                    unsigned bk[4];
                    ldm_x4(bk, &cK[(np * 16 + kRowN) * LDKH + kk * 16 + kColK]);
                    mma_f16(s[0][2 * np],     qf[kk][0], bk);
                    mma_f16(s[0][2 * np + 1], qf[kk][0], bk + 2);
                    mma_f16(s[1][2 * np],     qf[kk][1], bk);
                    mma_f16(s[1][2 * np + 1], qf[kk][1], bk + 2);
                }
            }

            // ---- scale + causal mask ----
            const float scale = 0.125f;
            if (kb * 64 + 63 > rowW) {
#pragma unroll
                for (int mt = 0; mt < 2; mt++) {
                    int r0 = rowW + mt * 16 + g;
                    int r1 = r0 + 8;
#pragma unroll
                    for (int nt = 0; nt < 8; nt++) {
                        int c0 = kb * 64 + nt * 8 + 2 * t;
                        s[mt][nt][0] = (c0     <= r0) ? s[mt][nt][0] * scale : -1e30f;
                        s[mt][nt][1] = (c0 + 1 <= r0) ? s[mt][nt][1] * scale : -1e30f;
                        s[mt][nt][2] = (c0     <= r1) ? s[mt][nt][2] * scale : -1e30f;
                        s[mt][nt][3] = (c0 + 1 <= r1) ? s[mt][nt][3] * scale : -1e30f;
                    }
                }
            } else {
#pragma unroll
                for (int mt = 0; mt < 2; mt++)
#pragma unroll
                    for (int nt = 0; nt < 8; nt++)
#pragma unroll
                        for (int j = 0; j < 4; j++) s[mt][nt][j] *= scale;
            }

            // ---- online softmax ----
#pragma unroll
            for (int mt = 0; mt < 2; mt++) {
                float mx0 = -1e30f, mx1 = -1e30f;
#pragma unroll
                for (int nt = 0; nt < 8; nt++) {
                    mx0 = fmaxf(mx0, fmaxf(s[mt][nt][0], s[mt][nt][1]));
                    mx1 = fmaxf(mx1, fmaxf(s[mt][nt][2], s[mt][nt][3]));
                }
                mx0 = fmaxf(mx0, __shfl_xor_sync(0xffffffffu, mx0, 1));
                mx0 = fmaxf(mx0, __shfl_xor_sync(0xffffffffu, mx0, 2));
                mx1 = fmaxf(mx1, __shfl_xor_sync(0xffffffffu, mx1, 1));
                mx1 = fmaxf(mx1, __shfl_xor_sync(0xffffffffu, mx1, 2));

                float mn0 = fmaxf(mS[mt][0], mx0), mn1 = fmaxf(mS[mt][1], mx1);
                float a0 = __expf(mS[mt][0] - mn0), a1 = __expf(mS[mt][1] - mn1);
                mS[mt][0] = mn0; mS[mt][1] = mn1;

                float sum0 = 0.f, sum1 = 0.f;
#pragma unroll
                for (int nt = 0; nt < 8; nt++) {
                    s[mt][nt][0] = __expf(s[mt][nt][0] - mn0);
                    s[mt][nt][1] = __expf(s[mt][nt][1] - mn0);
                    s[mt][nt][2] = __expf(s[mt][nt][2] - mn1);
                    s[mt][nt][3] = __expf(s[mt][nt][3] - mn1);
                    sum0 += s[mt][nt][0] + s[mt][nt][1];
                    sum1 += s[mt][nt][2] + s[mt][nt][3];
                }
                sum0 += __shfl_xor_sync(0xffffffffu, sum0, 1);
                sum0 += __shfl_xor_sync(0xffffffffu, sum0, 2);
                sum1 += __shfl_xor_sync(0xffffffffu, sum1, 1);
                sum1 += __shfl_xor_sync(0xffffffffu, sum1, 2);
                lS[mt][0] = lS[mt][0] * a0 + sum0;
                lS[mt][1] = lS[mt][1] * a1 + sum1;

#pragma unroll
                for (int nt = 0; nt < 8; nt++) {
                    o[mt][nt][0] *= a0; o[mt][nt][1] *= a0;
                    o[mt][nt][2] *= a1; o[mt][nt][3] *= a1;
                }
            }

            // ---- stage P (fp16) into per-warp smem [32][LDQH] ----
            __syncwarp();
#pragma unroll
            for (int mt = 0; mt < 2; mt++)
#pragma unroll
                for (int nt = 0; nt < 8; nt++) {
                    int c0 = nt * 8 + 2 * t;
                    *(unsigned*)&sP[(mt * 16 + g) * LDQH + c0]     = packh2(s[mt][nt][0], s[mt][nt][1]);
                    *(unsigned*)&sP[(mt * 16 + 8 + g) * LDQH + c0] = packh2(s[mt][nt][2], s[mt][nt][3]);
                }
            __syncwarp();

            // ---- O += P @ V (m32 x n64 x k64) ----
#pragma unroll
            for (int kk = 0; kk < 4; kk++) {
                unsigned pf[2][4];
                ldm_x4(pf[0], &sP[(aRow) * LDQH + kk * 16 + aCol]);
                ldm_x4(pf[1], &sP[(16 + aRow) * LDQH + kk * 16 + aCol]);
#pragma unroll
                for (int np = 0; np < 4; np++) {
                    unsigned bv[4];
                    ldm_x4t(bv, &cV[(kk * 16 + vRowK) * LDVH + np * 16 + vColN]);
                    mma_f16(o[0][2 * np],     pf[0], bv);
                    mma_f16(o[0][2 * np + 1], pf[0], bv + 2);
                    mma_f16(o[1][2 * np],     pf[1], bv);
                    mma_f16(o[1][2 * np + 1], pf[1], bv + 2);
                }
            }
        }
        __syncthreads();
    }

    // ---- epilogue: normalize, write y (fp16) ----
#pragma unroll
    for (int mt = 0; mt < 2; mt++) {
        float inv0 = 1.0f / lS[mt][0], inv1 = 1.0f / lS[mt][1];
        int r0 = rowW + mt * 16 + g;
        const size_t yr0 = ((size_t)(b * TSEQ) + r0) * CDIM + h * DH;
        const size_t yr1 = ((size_t)(b * TSEQ) + r0 + 8) * CDIM + h * DH;
#pragma unroll
        for (int nt = 0; nt < 8; nt++) {
            int c0 = nt * 8 + 2 * t;
            *(unsigned*)(y + yr0 + c0) = packh2(o[mt][nt][0] * inv0, o[mt][nt][1] * inv0);
            *(unsigned*)(y + yr1 + c0) = packh2(o[mt][nt][2] * inv1, o[mt][nt][3] * inv1);
        }
    }
}

// ---------------------------------------------------------------------------
extern "C" void kernel_launch(void* const* d_in, const int* in_sizes, int n_in,
                              void* d_out, int out_size)
{
    const float* x      = (const float*)d_in[0];
    const float* w_attn = (const float*)d_in[1];
    const float* b_attn = (const float*)d_in[2];
    const float* w_proj = (const float*)d_in[3];
    const float* b_proj = (const float*)d_in[4];
    float* out = (float*)d_out;

    __half *xh, *wah, *wph, *qkv, *yb;
    cudaGetSymbolAddress((void**)&xh, g_xh);
    cudaGetSymbolAddress((void**)&wah, g_wah);
    cudaGetSymbolAddress((void**)&wph, g_wph);
    cudaGetSymbolAddress((void**)&qkv, g_qkv);
    cudaGetSymbolAddress((void**)&yb, g_y);

    cudaFuncSetAttribute(gemm_f16_bias<true>,
                         cudaFuncAttributeMaxDynamicSharedMemorySize, GEMM_SMEM_B);
    cudaFuncSetAttribute(gemm_f16_bias<false>,
                         cudaFuncAttributeMaxDynamicSharedMemorySize, GEMM_SMEM_B);
    cudaFuncSetAttribute(attn_flash_mma,
                         cudaFuncAttributeMaxDynamicSharedMemorySize, ATTN_SMEM_B);

    const int M = BSZ * TSEQ;   // 4096

    // 0) pre-convert inputs to fp16
    const int nx  = M * CDIM / 8;             // 524288
    const int nwa = CDIM * 3 * CDIM / 8;      // 393216
    const int nwp = CDIM * CDIM / 8;          // 131072
    cvt_f16<<<(nx  + 255) / 256, 256>>>(x,      xh,  nx);
    cvt_f16<<<(nwa + 255) / 256, 256>>>(w_attn, wah, nwa);
    cvt_f16<<<(nwp + 255) / 256, 256>>>(w_proj, wph, nwp);

    // 1) qkv = x @ w_attn + b_attn     [4096, 3072]  (fp16 out)
    gemm_f16_bias<true><<<dim3((3 * CDIM) / 128, M / 128), 128, GEMM_SMEM_B>>>(
        xh, wah, b_attn, qkv, M, 3 * CDIM, CDIM);

    // 2) flash attention -> y (fp16)   [4096, 1024]
    attn_flash_mma<<<dim3(TSEQ / 128, HN, BSZ), 128, ATTN_SMEM_B>>>(qkv, yb);

    // 3) out = y @ w_proj + b_proj     [4096, 1024]  (fp32 out)
    gemm_f16_bias<false><<<dim3(CDIM / 128, M / 128), 128, GEMM_SMEM_B>>>(
        yb, wph, b_proj, out, M, CDIM, CDIM);
}